// round 15
// baseline (speedup 1.0000x reference)
#include <cuda_runtime.h>
#include <cstdint>

// GCNConv: out[dst] += feat[src] * w   (edge_dst sorted ascending)
// feat: [N=50000, 64] f32, indices int32.
//
// R9:  36.5us, MLP~1, occ 90%  -> latency-exposed.
// R13: 33.5us, MLP 4 via 4-edge chunking, but regs 50 -> occ 46% ate the win.
// This (unmeasured resubmit): __launch_bounds__(256, 6) caps regs ~42 ->
// occ ~75% while keeping the 4 independent LDG.128 gathers per trip (MLP 4).
//  - 16-lane half-warp owns an edge; lane hl owns cols 4hl..4hl+3 (float4).
//  - Sorted dst => register run accumulation, atomicAdd only on run boundary.

#define N_NODES 50000
#define D_FEAT 64
#define EPW 64                 // edges per warp
#define HALF_E (EPW / 2)       // 32 edges per half-warp
#define WARPS_PER_BLOCK 8
#define EPB (EPW * WARPS_PER_BLOCK)  // 512 edges per block

__device__ __forceinline__ void flush_run(float* __restrict__ out, int dst,
                                          int col, float4& acc) {
    float* p = out + (size_t)dst * D_FEAT + col;
    atomicAdd(p + 0, acc.x);
    atomicAdd(p + 1, acc.y);
    atomicAdd(p + 2, acc.z);
    atomicAdd(p + 3, acc.w);
    acc.x = 0.0f; acc.y = 0.0f; acc.z = 0.0f; acc.w = 0.0f;
}

__device__ __forceinline__ void accum(float4& acc, const float4 f, const float w) {
    acc.x = fmaf(f.x, w, acc.x);
    acc.y = fmaf(f.y, w, acc.y);
    acc.z = fmaf(f.z, w, acc.z);
    acc.w = fmaf(f.w, w, acc.w);
}

__global__ __launch_bounds__(256, 6) void gcn_gather_scatter(
    const float* __restrict__ feat,
    const float* __restrict__ ew,
    const int* __restrict__ esrc,
    const int* __restrict__ edst,
    float* __restrict__ out,
    int E) {

    __shared__ int2 s_sw[EPB];   // (src, w bits)
    __shared__ int  s_dst[EPB];

    const int blockE0 = blockIdx.x * EPB;
    const int nLocal  = min(EPB, E - blockE0);

    // Coalesced metadata stage.
    for (int i = threadIdx.x; i < nLocal; i += blockDim.x) {
        const int e = blockE0 + i;
        s_sw[i]  = make_int2(esrc[e], __float_as_int(ew[e]));
        s_dst[i] = edst[e];
    }
    __syncthreads();

    const int warp = threadIdx.x >> 5;
    const int lane = threadIdx.x & 31;
    const int half = lane >> 4;
    const int hl   = lane & 15;
    const int col  = hl * 4;

    const int base = warp * EPW + half * HALF_E;
    if (base >= nLocal) return;
    const int cnt = min(HALF_E, nLocal - base);

    float4 acc = make_float4(0.0f, 0.0f, 0.0f, 0.0f);
    int cur = s_dst[base];

    int j = 0;
    // Main: 4 edges per trip; all loads issued before any branch.
    for (; j + 4 <= cnt; j += 4) {
        const int i = base + j;
        const int2 sw0 = s_sw[i + 0];
        const int2 sw1 = s_sw[i + 1];
        const int2 sw2 = s_sw[i + 2];
        const int2 sw3 = s_sw[i + 3];
        const int  d0  = s_dst[i + 0];
        const int  d1  = s_dst[i + 1];
        const int  d2  = s_dst[i + 2];
        const int  d3  = s_dst[i + 3];
        // 4 independent gathers -> MLP 4.
        const float4 f0 = *reinterpret_cast<const float4*>(feat + (size_t)sw0.x * D_FEAT + col);
        const float4 f1 = *reinterpret_cast<const float4*>(feat + (size_t)sw1.x * D_FEAT + col);
        const float4 f2 = *reinterpret_cast<const float4*>(feat + (size_t)sw2.x * D_FEAT + col);
        const float4 f3 = *reinterpret_cast<const float4*>(feat + (size_t)sw3.x * D_FEAT + col);

        if (d0 != cur) { flush_run(out, cur, col, acc); cur = d0; }
        accum(acc, f0, __int_as_float(sw0.y));
        if (d1 != cur) { flush_run(out, cur, col, acc); cur = d1; }
        accum(acc, f1, __int_as_float(sw1.y));
        if (d2 != cur) { flush_run(out, cur, col, acc); cur = d2; }
        accum(acc, f2, __int_as_float(sw2.y));
        if (d3 != cur) { flush_run(out, cur, col, acc); cur = d3; }
        accum(acc, f3, __int_as_float(sw3.y));
    }
    // Tail.
    for (; j < cnt; ++j) {
        const int i = base + j;
        const int2 sw = s_sw[i];
        const int  d  = s_dst[i];
        const float4 f = *reinterpret_cast<const float4*>(feat + (size_t)sw.x * D_FEAT + col);
        if (d != cur) { flush_run(out, cur, col, acc); cur = d; }
        accum(acc, f, __int_as_float(sw.y));
    }
    flush_run(out, cur, col, acc);
}

extern "C" void kernel_launch(void* const* d_in, const int* in_sizes, int n_in,
                              void* d_out, int out_size) {
    const float* feat = (const float*)d_in[0];
    const float* ew   = (const float*)d_in[1];
    const int*   esrc = (const int*)d_in[2];
    const int*   edst = (const int*)d_in[3];
    float*       out  = (float*)d_out;

    const int E = in_sizes[1];  // edge_weight element count

    // d_out is poisoned; zero before accumulation (graph-capturable memset).
    cudaMemsetAsync(d_out, 0, (size_t)out_size * sizeof(float), 0);

    const int blocks = (E + EPB - 1) / EPB;
    gcn_gather_scatter<<<blocks, 256>>>(feat, ew, esrc, edst, out, E);
}